// round 15
// baseline (speedup 1.0000x reference)
#include <cuda_runtime.h>
#include <cuda_bf16.h>
#include <math.h>

#define T_STEPS 100000
#define S_DIM   200
#define N_DIM   215

// ---- device scratch (static; no runtime allocation) ----
__device__ float g_pre_f[T_STEPS * S_DIM];
__device__ float g_pre_i[T_STEPS * S_DIM];
__device__ float g_cand [T_STEPS * S_DIM];
__device__ float g_sfinal[S_DIM];

// ---- helpers ----
__device__ __forceinline__ unsigned smem_u32(const void* p) {
    unsigned a;
    asm("{ .reg .u64 t; cvta.to.shared.u64 t, %1; cvt.u32.u64 %0, t; }"
        : "=r"(a) : "l"(p));
    return a;
}
__device__ __forceinline__ unsigned mapa_u32(unsigned a, unsigned rank) {
    unsigned d;
    asm("mapa.shared::cluster.u32 %0, %1, %2;" : "=r"(d) : "r"(a), "r"(rank));
    return d;
}
__device__ __forceinline__ void st_shared_cluster_b64(unsigned addr,
                                                      unsigned long long v) {
    asm volatile("st.shared::cluster.b64 [%0], %1;"
                 :: "r"(addr), "l"(v) : "memory");
}
__device__ __forceinline__ unsigned long long ld_volatile_shared_b64(unsigned addr) {
    unsigned long long v;
    asm volatile("ld.volatile.shared.b64 %0, [%1];"
                 : "=l"(v) : "r"(addr) : "memory");
    return v;
}
__device__ __forceinline__ unsigned long long pack2(float x, float y) {
    unsigned long long r;
    asm("mov.b64 %0, {%1, %2};" : "=l"(r) : "f"(x), "f"(y));
    return r;
}
__device__ __forceinline__ float2 unpack2(unsigned long long v) {
    float2 f;
    asm("mov.b64 {%0, %1}, %2;" : "=f"(f.x), "=f"(f.y) : "l"(v));
    return f;
}
__device__ __forceinline__ unsigned long long tag_pack(unsigned tag, float val) {
    unsigned long long r;
    asm("mov.b64 %0, {%1, %2};" : "=l"(r) : "f"(val), "r"(tag));
    return r;  // lo = value, hi = tag
}
#define FMA2(acc, a, b) \
    asm("fma.rn.f32x2 %0, %1, %2, %0;" : "+l"(acc) : "l"(a), "l"(b))
#define ADD2(out, a, b) \
    asm("add.rn.f32x2 %0, %1, %2;" : "=l"(out) : "l"(a), "l"(b))

#define CLUSTER_ARRIVE() \
    asm volatile("barrier.cluster.arrive.aligned;" ::: "memory")
#define CLUSTER_WAIT() \
    asm volatile("barrier.cluster.wait.aligned;" ::: "memory")

// ============================================================
// Phase 1: the three track GEMMs. grid (3125,3), block 256.
// ============================================================
#define TILE_T 32
#define KCHUNK 43   // 5*43 = 215

__global__ __launch_bounds__(256) void pre_kernel(
    const float* __restrict__ track,
    const float* __restrict__ Wf, const float* __restrict__ bf,
    const float* __restrict__ Wi, const float* __restrict__ bi,
    const float* __restrict__ Wc, const float* __restrict__ bc)
{
    __shared__ float sW[KCHUNK * S_DIM];
    __shared__ float sT[TILE_T * KCHUNK];
    const int mat = blockIdx.y;
    const int t0  = blockIdx.x * TILE_T;
    const int tid = threadIdx.x;
    const float* W   = (mat == 0) ? Wf : (mat == 1) ? Wi : Wc;
    const float* bia = (mat == 0) ? bf : (mat == 1) ? bi : bc;
    float* out       = (mat == 0) ? g_pre_f : (mat == 1) ? g_pre_i : g_cand;

    float acc[TILE_T];
    #pragma unroll
    for (int i = 0; i < TILE_T; i++) acc[i] = 0.0f;

    for (int c = 0; c < 5; c++) {
        const int k0 = c * KCHUNK;
        for (int idx = tid; idx < KCHUNK * S_DIM; idx += 256) {
            int r = idx / S_DIM, col = idx - r * S_DIM;
            sW[idx] = W[(k0 + r) * S_DIM + col];
        }
        for (int idx = tid; idx < TILE_T * KCHUNK; idx += 256) {
            int tt = idx / KCHUNK, kk = idx - tt * KCHUNK;
            sT[idx] = track[(t0 + tt) * N_DIM + k0 + kk];
        }
        __syncthreads();
        if (tid < S_DIM) {
            for (int kk = 0; kk < KCHUNK; kk++) {
                float wv = sW[kk * S_DIM + tid];
                #pragma unroll
                for (int tt = 0; tt < TILE_T; tt++)
                    acc[tt] = fmaf(sT[tt * KCHUNK + kk], wv, acc[tt]);
            }
        }
        __syncthreads();
    }
    if (tid < S_DIM) {
        float bv = bia[tid];
        #pragma unroll 4
        for (int tt = 0; tt < TILE_T; tt++) {
            float v = acc[tt] + bv;
            if (mat == 2) v = tanhf(v);
            out[(t0 + tt) * S_DIM + tid] = v;
        }
    }
}

// ============================================================
// Phase 2: sequential scan. 2-CTA cluster, 448 threads/CTA.
// Warp-aligned k-half layout: warps 0-6 h=0, warps 7-13 h=1;
// lanes = 32 consecutive columns. All lanes of a warp read the
// SAME 16B state chunk -> broadcast LDS, 1 wavefront (crossbar
// 650 -> 350 cyc/step vs interleaved layout). Cross-half combine
// via s_part STS/LDS (replaces shfl). Exchange = R13's proven
// tagged-packet scheme: owner pushes {tag=t+1,val} b64 into the
// peer's inbox [t&1][j] via st.shared::cluster (single-copy
// atomic, data is its own flag); consumer polls its OWN smem
// slot with ld.volatile.shared. No barriers in the loop.
// rank0: u = s_old * sigmoid(pre_f + s@Wf_s)
// rank1: v = sigmoid(pre_i + s@Wi_s) * cand ; s_new = u + v.
// ============================================================
__global__ void __cluster_dims__(2, 1, 1) __launch_bounds__(448, 1)
scan_kernel(const float* __restrict__ Wf, const float* __restrict__ Wi,
            const float* __restrict__ state0)
{
    __shared__ __align__(16) float s_state[S_DIM];
    __shared__ __align__(16) float s_part[S_DIM];
    __shared__ __align__(16) unsigned long long s_inbox[2][S_DIM];

    const int tid  = threadIdx.x;
    const int wid  = tid >> 5;
    const int lane = tid & 31;
    unsigned rank;
    asm("mov.u32 %0, %%cluster_ctarank;" : "=r"(rank));
    const unsigned peerR = rank ^ 1u;

    const int  h     = (wid >= 7) ? 1 : 0;          // k-half (warp-aligned)
    const int  jw    = h ? (wid - 7) : wid;
    const int  j     = jw * 32 + lane;              // column
    const bool valid = (j < S_DIM);
    const bool own   = valid && (h == 0);

    // ---- weights: 50 f32x2 pairs for k in [h*100, h*100+100) ----
    const float* W = (rank == 0) ? Wf : Wi;         // rows [215,415)
    const int kbase = N_DIM + h * 100;
    unsigned long long w[50];
    #pragma unroll
    for (int i = 0; i < 50; i++) {
        float a = valid ? W[(kbase + 2 * i    ) * S_DIM + j] : 0.0f;
        float b = valid ? W[(kbase + 2 * i + 1) * S_DIM + j] : 0.0f;
        w[i] = pack2(a, b);
    }

    // init: state + zero-tagged inbox slots
    if (tid < S_DIM) {
        s_state[tid] = state0[tid];
        s_inbox[0][tid] = 0ull;
        s_inbox[1][tid] = 0ull;
    }
    __syncthreads();
    CLUSTER_ARRIVE();   // one-time: init visible cluster-wide before any push
    CLUSTER_WAIT();

    // remote addresses of MY column's slot in the PEER's inbox (both parities)
    const int jj = own ? j : 0;
    const unsigned pi0 = mapa_u32(smem_u32(&s_inbox[0][jj]), peerR);
    const unsigned pi1 = mapa_u32(smem_u32(&s_inbox[1][jj]), peerR);
    // local addresses of my own inbox slot (poll targets)
    const unsigned li0 = smem_u32(&s_inbox[0][jj]);
    const unsigned li1 = smem_u32(&s_inbox[1][jj]);

    const float* pre = (rank == 0) ? g_pre_f : g_pre_i;
    float p_cur = 0.0f, c_cur = 0.0f;
    if (own) {
        p_cur = __ldcg(pre + j);
        if (rank == 1) c_cur = __ldcg(g_cand + j);
    }

    for (int t = 0; t < T_STEPS; t++) {
        const int b = t & 1;

        // prefetch next step's streams (hides DRAM latency)
        float p_next = 0.0f, c_next = 0.0f;
        if (own) {
            int tn = (t + 1 < T_STEPS) ? (t + 1) : (T_STEPS - 1);
            p_next = __ldcg(pre + tn * S_DIM + j);
            if (rank == 1) c_next = __ldcg(g_cand + tn * S_DIM + j);
        }

        // ---- partial matvec: 100 MACs as 50 f32x2 FMAs, broadcast LDS ----
        unsigned long long a0 = 0ull, a1 = 0ull;
        const ulonglong2* s4 = (const ulonglong2*)s_state + h * 25;
        #pragma unroll
        for (int i = 0; i < 25; i++) {
            ulonglong2 sv = s4[i];
            FMA2(a0, w[2 * i    ], sv.x);
            FMA2(a1, w[2 * i + 1], sv.y);
        }
        unsigned long long r01;
        ADD2(r01, a0, a1);
        float2 f = unpack2(r01);
        float zp = f.x + f.y;

        // cross-half combine through smem (stride-1, conflict-free)
        if (valid && h == 1) s_part[j] = zp;
        __syncthreads();

        if (own) {
            float z = zp + s_part[j] + p_cur;
            float g = __fdividef(1.0f, 1.0f + __expf(-z));
            float contrib = (rank == 0) ? (s_state[j] * g) : (g * c_cur);

            // push tagged packet into the peer's inbox (data = its own flag)
            const unsigned tag = (unsigned)(t + 1);
            st_shared_cluster_b64(b ? pi1 : pi0, tag_pack(tag, contrib));

            // poll MY OWN smem slot for the peer's packet
            const unsigned slot = b ? li1 : li0;
            unsigned long long pkt = ld_volatile_shared_b64(slot);
            while ((unsigned)(pkt >> 32) != tag)
                pkt = ld_volatile_shared_b64(slot);
            float pv = __uint_as_float((unsigned)pkt);

            s_state[j] = contrib + pv;
        }
        __syncthreads();

        p_cur = p_next; c_cur = c_next;
    }

    if (rank == 0 && own) g_sfinal[j] = s_state[j];
    // exit sync: no CTA may die while its peer might still push into it
    CLUSTER_ARRIVE();
    CLUSTER_WAIT();
}

// ============================================================
// Phase 3: output head. 1 block, 256 threads.
// ============================================================
__global__ __launch_bounds__(256) void head_kernel(
    const float* __restrict__ W1, const float* __restrict__ b1,
    const float* __restrict__ W2, const float* __restrict__ b2,
    float* __restrict__ out)
{
    __shared__ float s_s[S_DIM], s_h[S_DIM], s_red[256];
    const int tid = threadIdx.x;
    if (tid < S_DIM) s_s[tid] = g_sfinal[tid];
    __syncthreads();

    if (tid < S_DIM) {
        float a = b1[tid];
        for (int k = 0; k < S_DIM; k++) a = fmaf(s_s[k], W1[k * S_DIM + tid], a);
        s_h[tid] = fmaxf(a, 0.0f);
    }
    __syncthreads();
    float h2 = 0.0f;
    if (tid < S_DIM) {
        float a = b2[tid];
        for (int k = 0; k < S_DIM; k++) a = fmaf(s_h[k], W2[k * S_DIM + tid], a);
        h2 = fmaxf(a, 0.0f);
    }
    s_red[tid] = (tid < S_DIM) ? h2 : -1e30f;
    __syncthreads();
    for (int s = 128; s > 0; s >>= 1) {
        if (tid < s) s_red[tid] = fmaxf(s_red[tid], s_red[tid + s]);
        __syncthreads();
    }
    float m = s_red[0];
    __syncthreads();
    s_red[tid] = (tid < S_DIM) ? expf(h2 - m) : 0.0f;
    __syncthreads();
    for (int s = 128; s > 0; s >>= 1) {
        if (tid < s) s_red[tid] += s_red[tid + s];
        __syncthreads();
    }
    float lse = logf(s_red[0]);
    if (tid < S_DIM) out[tid] = h2 - m - lse;
}

// ============================================================
extern "C" void kernel_launch(void* const* d_in, const int* in_sizes, int n_in,
                              void* d_out, int out_size) {
    const float* track  = (const float*)d_in[0];
    const float* state0 = (const float*)d_in[1];
    const float* Wf     = (const float*)d_in[2];
    const float* bf     = (const float*)d_in[3];
    const float* Wi     = (const float*)d_in[4];
    const float* bi     = (const float*)d_in[5];
    const float* Wc     = (const float*)d_in[6];
    const float* bc     = (const float*)d_in[7];
    const float* W1     = (const float*)d_in[8];
    const float* b1     = (const float*)d_in[9];
    const float* W2     = (const float*)d_in[10];
    const float* b2     = (const float*)d_in[11];
    float* out = (float*)d_out;

    dim3 g(T_STEPS / TILE_T, 3);
    pre_kernel<<<g, 256>>>(track, Wf, bf, Wi, bi, Wc, bc);
    scan_kernel<<<2, 448>>>(Wf, Wi, state0);
    head_kernel<<<1, 256>>>(W1, b1, W2, b2, out);
}

// round 16
// speedup vs baseline: 1.0315x; 1.0315x over previous
#include <cuda_runtime.h>
#include <cuda_bf16.h>
#include <math.h>

#define T_STEPS 100000
#define S_DIM   200
#define N_DIM   215

// ---- device scratch (static; no runtime allocation) ----
__device__ float g_pre_f[T_STEPS * S_DIM];
__device__ float g_pre_i[T_STEPS * S_DIM];
__device__ float g_cand [T_STEPS * S_DIM];
__device__ float g_sfinal[S_DIM];

// ---- helpers ----
__device__ __forceinline__ unsigned smem_u32(const void* p) {
    unsigned a;
    asm("{ .reg .u64 t; cvta.to.shared.u64 t, %1; cvt.u32.u64 %0, t; }"
        : "=r"(a) : "l"(p));
    return a;
}
__device__ __forceinline__ unsigned mapa_u32(unsigned a, unsigned rank) {
    unsigned d;
    asm("mapa.shared::cluster.u32 %0, %1, %2;" : "=r"(d) : "r"(a), "r"(rank));
    return d;
}
__device__ __forceinline__ void st_shared_cluster_b64(unsigned addr,
                                                      unsigned long long v) {
    asm volatile("st.shared::cluster.b64 [%0], %1;"
                 :: "r"(addr), "l"(v) : "memory");
}
__device__ __forceinline__ unsigned long long ld_volatile_shared_b64(unsigned addr) {
    unsigned long long v;
    asm volatile("ld.volatile.shared.b64 %0, [%1];"
                 : "=l"(v) : "r"(addr) : "memory");
    return v;
}
__device__ __forceinline__ unsigned long long pack2(float x, float y) {
    unsigned long long r;
    asm("mov.b64 %0, {%1, %2};" : "=l"(r) : "f"(x), "f"(y));
    return r;
}
__device__ __forceinline__ float2 unpack2(unsigned long long v) {
    float2 f;
    asm("mov.b64 {%0, %1}, %2;" : "=f"(f.x), "=f"(f.y) : "l"(v));
    return f;
}
__device__ __forceinline__ unsigned long long tag_pack(unsigned tag, float val) {
    unsigned long long r;
    asm("mov.b64 %0, {%1, %2};" : "=l"(r) : "f"(val), "r"(tag));
    return r;  // lo = value, hi = tag
}
#define FMA2(acc, a, b) \
    asm("fma.rn.f32x2 %0, %1, %2, %0;" : "+l"(acc) : "l"(a), "l"(b))
#define ADD2(out, a, b) \
    asm("add.rn.f32x2 %0, %1, %2;" : "=l"(out) : "l"(a), "l"(b))

#define CLUSTER_ARRIVE() \
    asm volatile("barrier.cluster.arrive.aligned;" ::: "memory")
#define CLUSTER_WAIT() \
    asm volatile("barrier.cluster.wait.aligned;" ::: "memory")

// ============================================================
// Phase 1: the three track GEMMs. grid (3125,3), block 256.
// ============================================================
#define TILE_T 32
#define KCHUNK 43   // 5*43 = 215

__global__ __launch_bounds__(256) void pre_kernel(
    const float* __restrict__ track,
    const float* __restrict__ Wf, const float* __restrict__ bf,
    const float* __restrict__ Wi, const float* __restrict__ bi,
    const float* __restrict__ Wc, const float* __restrict__ bc)
{
    __shared__ float sW[KCHUNK * S_DIM];
    __shared__ float sT[TILE_T * KCHUNK];
    const int mat = blockIdx.y;
    const int t0  = blockIdx.x * TILE_T;
    const int tid = threadIdx.x;
    const float* W   = (mat == 0) ? Wf : (mat == 1) ? Wi : Wc;
    const float* bia = (mat == 0) ? bf : (mat == 1) ? bi : bc;
    float* out       = (mat == 0) ? g_pre_f : (mat == 1) ? g_pre_i : g_cand;

    float acc[TILE_T];
    #pragma unroll
    for (int i = 0; i < TILE_T; i++) acc[i] = 0.0f;

    for (int c = 0; c < 5; c++) {
        const int k0 = c * KCHUNK;
        for (int idx = tid; idx < KCHUNK * S_DIM; idx += 256) {
            int r = idx / S_DIM, col = idx - r * S_DIM;
            sW[idx] = W[(k0 + r) * S_DIM + col];
        }
        for (int idx = tid; idx < TILE_T * KCHUNK; idx += 256) {
            int tt = idx / KCHUNK, kk = idx - tt * KCHUNK;
            sT[idx] = track[(t0 + tt) * N_DIM + k0 + kk];
        }
        __syncthreads();
        if (tid < S_DIM) {
            for (int kk = 0; kk < KCHUNK; kk++) {
                float wv = sW[kk * S_DIM + tid];
                #pragma unroll
                for (int tt = 0; tt < TILE_T; tt++)
                    acc[tt] = fmaf(sT[tt * KCHUNK + kk], wv, acc[tt]);
            }
        }
        __syncthreads();
    }
    if (tid < S_DIM) {
        float bv = bia[tid];
        #pragma unroll 4
        for (int tt = 0; tt < TILE_T; tt++) {
            float v = acc[tt] + bv;
            if (mat == 2) v = tanhf(v);
            out[(t0 + tt) * S_DIM + tid] = v;
        }
    }
}

// ============================================================
// Phase 2: sequential scan. 2-CTA cluster, 416 threads/CTA.
// Flight-hiding split (R12's algebra + R13's exchange):
//   z = W^T s  =  W^T(my prev contrib)  [A-pass, local data]
//              +  W^T(peer prev contrib) [B-pass, after poll]
// Step t: A-pass over s_mine[p] (ready at step start) runs WHILE
// the peer's tagged packet (pushed at its step t-1) is in flight;
// owners then poll (flight already elapsed), STS s_peer[p][j],
// sync, B-pass, shfl-combine, gate, push tag t+1 + store s_mine,
// sync. Inbox[0] primed with tag-0 packets = initial peer part,
// so the loop is branch-uniform from t=0. Slot reuse safe: peer
// consumes tag t+1 before producing tag t+2, which I consume
// before producing tag t+3 into the same-parity slot.
// rank0: u = s_old * sigmoid(pre_f + z); s_old = mine_prev + pv
// rank1: v = sigmoid(pre_i + z) * cand ; s_new = u + v.
// ============================================================
__global__ void __cluster_dims__(2, 1, 1) __launch_bounds__(416, 1)
scan_kernel(const float* __restrict__ Wf, const float* __restrict__ Wi,
            const float* __restrict__ state0)
{
    __shared__ __align__(16) float s_mine[2][S_DIM];
    __shared__ __align__(16) float s_peer[2][S_DIM];
    __shared__ __align__(16) unsigned long long s_inbox[2][S_DIM];

    const int tid = threadIdx.x;
    unsigned rank;
    asm("mov.u32 %0, %%cluster_ctarank;" : "=r"(rank));
    const unsigned peerR = rank ^ 1u;

    const bool act = (tid < 400);
    const int  j   = act ? (tid >> 1) : 0;   // output column
    const int  h   = tid & 1;                // k-half
    const bool own = act && (h == 0);

    // ---- load this CTA's recurrent matrix into registers ----
    const float* W = (rank == 0) ? Wf : Wi;  // rows [215,415) = recurrent part
    const int kbase = N_DIM + h * 100;
    unsigned long long w[50];
    #pragma unroll
    for (int i = 0; i < 50; i++) {
        float a = act ? W[(kbase + 2 * i    ) * S_DIM + j] : 0.0f;
        float b = act ? W[(kbase + 2 * i + 1) * S_DIM + j] : 0.0f;
        w[i] = pack2(a, b);
    }

    // init: s_0 split into mine/peer parts; inbox[0] primed tag-0
    float mine_prev = 0.0f;
    if (own) {
        float s0 = state0[j];
        float minePart = (rank == 0) ? s0 : 0.0f;
        float peerPart = (rank == 0) ? 0.0f : s0;
        mine_prev = minePart;
        s_mine[0][j] = minePart;
        s_mine[1][j] = 0.0f;
        s_peer[0][j] = 0.0f;
        s_peer[1][j] = 0.0f;
        s_inbox[0][j] = tag_pack(0u, peerPart);   // t=0 poll passes instantly
        s_inbox[1][j] = 0xFFFFFFFF00000000ull;    // never matches a tag
    }
    __syncthreads();
    CLUSTER_ARRIVE();   // one-time: init visible cluster-wide before any push
    CLUSTER_WAIT();

    // remote addresses of MY column's slot in the PEER's inbox (both parities)
    const int jj = own ? j : 0;
    const unsigned pi0 = mapa_u32(smem_u32(&s_inbox[0][jj]), peerR);
    const unsigned pi1 = mapa_u32(smem_u32(&s_inbox[1][jj]), peerR);
    // local addresses of my own inbox slot (poll targets)
    const unsigned li0 = smem_u32(&s_inbox[0][jj]);
    const unsigned li1 = smem_u32(&s_inbox[1][jj]);

    const float* pre = (rank == 0) ? g_pre_f : g_pre_i;
    float p_cur = 0.0f, c_cur = 0.0f;
    if (own) {
        p_cur = __ldcg(pre + j);
        if (rank == 1) c_cur = __ldcg(g_cand + j);
    }

    for (int t = 0; t < T_STEPS; t++) {
        const int p = t & 1;

        // prefetch next step's streams (hides DRAM latency)
        float p_next = 0.0f, c_next = 0.0f;
        if (own) {
            int tn = (t + 1 < T_STEPS) ? (t + 1) : (T_STEPS - 1);
            p_next = __ldcg(pre + tn * S_DIM + j);
            if (rank == 1) c_next = __ldcg(g_cand + tn * S_DIM + j);
        }

        // ---- A-pass: W^T (my prev contribs) — local, flight overlaps ----
        unsigned long long a0 = 0ull, a1 = 0ull;
        {
            const ulonglong2* s4 = (const ulonglong2*)s_mine[p] + h * 25;
            #pragma unroll
            for (int i = 0; i < 25; i++) {
                ulonglong2 sv = s4[i];
                FMA2(a0, w[2 * i    ], sv.x);
                FMA2(a1, w[2 * i + 1], sv.y);
            }
        }

        // ---- poll peer's contrib (tag t); flight already elapsed ----
        float pv = 0.0f;
        if (own) {
            const unsigned slot = p ? li1 : li0;
            unsigned long long pkt = ld_volatile_shared_b64(slot);
            while ((unsigned)(pkt >> 32) != (unsigned)t)
                pkt = ld_volatile_shared_b64(slot);
            pv = __uint_as_float((unsigned)pkt);
            s_peer[p][j] = pv;
        }
        __syncthreads();   // s_peer[p] fully assembled for B-pass

        // ---- B-pass: W^T (peer prev contribs) ----
        {
            const ulonglong2* s4 = (const ulonglong2*)s_peer[p] + h * 25;
            #pragma unroll
            for (int i = 0; i < 25; i++) {
                ulonglong2 sv = s4[i];
                FMA2(a0, w[2 * i    ], sv.x);
                FMA2(a1, w[2 * i + 1], sv.y);
            }
        }
        unsigned long long r01;
        ADD2(r01, a0, a1);
        float2 f = unpack2(r01);
        float zp = f.x + f.y;
        float z  = zp + __shfl_xor_sync(0xFFFFFFFFu, zp, 1);

        if (own) {
            z += p_cur;
            float g = __fdividef(1.0f, 1.0f + __expf(-z));
            float contrib;
            if (rank == 0) {
                float s_old = mine_prev + pv;     // registers only
                contrib = s_old * g;
            } else {
                contrib = g * c_cur;
            }
            mine_prev = contrib;
            s_mine[p ^ 1][j] = contrib;
            // push tagged packet for the peer's step t+1
            st_shared_cluster_b64(p ? pi0 : pi1,
                                  tag_pack((unsigned)(t + 1), contrib));
        }
        __syncthreads();   // s_mine[p^1] visible for next A-pass

        p_cur = p_next; c_cur = c_next;
    }

    // final state: s_T = my contrib(tag T) + peer contrib(tag T)
    if (rank == 0 && own) {
        const unsigned slot = (T_STEPS & 1) ? li1 : li0;
        unsigned long long pkt = ld_volatile_shared_b64(slot);
        while ((unsigned)(pkt >> 32) != (unsigned)T_STEPS)
            pkt = ld_volatile_shared_b64(slot);
        g_sfinal[j] = mine_prev + __uint_as_float((unsigned)pkt);
    }
    // exit sync: no CTA may die while its peer might still push into it
    CLUSTER_ARRIVE();
    CLUSTER_WAIT();
}

// ============================================================
// Phase 3: output head. 1 block, 256 threads.
// ============================================================
__global__ __launch_bounds__(256) void head_kernel(
    const float* __restrict__ W1, const float* __restrict__ b1,
    const float* __restrict__ W2, const float* __restrict__ b2,
    float* __restrict__ out)
{
    __shared__ float s_s[S_DIM], s_h[S_DIM], s_red[256];
    const int tid = threadIdx.x;
    if (tid < S_DIM) s_s[tid] = g_sfinal[tid];
    __syncthreads();

    if (tid < S_DIM) {
        float a = b1[tid];
        for (int k = 0; k < S_DIM; k++) a = fmaf(s_s[k], W1[k * S_DIM + tid], a);
        s_h[tid] = fmaxf(a, 0.0f);
    }
    __syncthreads();
    float h2 = 0.0f;
    if (tid < S_DIM) {
        float a = b2[tid];
        for (int k = 0; k < S_DIM; k++) a = fmaf(s_h[k], W2[k * S_DIM + tid], a);
        h2 = fmaxf(a, 0.0f);
    }
    s_red[tid] = (tid < S_DIM) ? h2 : -1e30f;
    __syncthreads();
    for (int s = 128; s > 0; s >>= 1) {
        if (tid < s) s_red[tid] = fmaxf(s_red[tid], s_red[tid + s]);
        __syncthreads();
    }
    float m = s_red[0];
    __syncthreads();
    s_red[tid] = (tid < S_DIM) ? expf(h2 - m) : 0.0f;
    __syncthreads();
    for (int s = 128; s > 0; s >>= 1) {
        if (tid < s) s_red[tid] += s_red[tid + s];
        __syncthreads();
    }
    float lse = logf(s_red[0]);
    if (tid < S_DIM) out[tid] = h2 - m - lse;
}

// ============================================================
extern "C" void kernel_launch(void* const* d_in, const int* in_sizes, int n_in,
                              void* d_out, int out_size) {
    const float* track  = (const float*)d_in[0];
    const float* state0 = (const float*)d_in[1];
    const float* Wf     = (const float*)d_in[2];
    const float* bf     = (const float*)d_in[3];
    const float* Wi     = (const float*)d_in[4];
    const float* bi     = (const float*)d_in[5];
    const float* Wc     = (const float*)d_in[6];
    const float* bc     = (const float*)d_in[7];
    const float* W1     = (const float*)d_in[8];
    const float* b1     = (const float*)d_in[9];
    const float* W2     = (const float*)d_in[10];
    const float* b2     = (const float*)d_in[11];
    float* out = (float*)d_out;

    dim3 g(T_STEPS / TILE_T, 3);
    pre_kernel<<<g, 256>>>(track, Wf, bf, Wi, bi, Wc, bc);
    scan_kernel<<<2, 416>>>(Wf, Wi, state0);
    head_kernel<<<1, 256>>>(W1, b1, W2, b2, out);
}